// round 8
// baseline (speedup 1.0000x reference)
#include <cuda_runtime.h>
#include <cuda_fp16.h>
#include <cstdint>

// ============================================================
// Problem constants
// ============================================================
#define NB 4096   // batch
#define NI 1024   // input dim
#define NO 1024   // output dim
#define K5 5      // control points per edge (j=0 basis column identically 0)
#define K4 4      // effective nonzero control points
#define KP4 (NI*K4)  // 4096 = effective GEMM reduction dim

// GEMM tiling: BM=BN=128, 256 threads, 2 CTAs/SM
#define BM 128
#define BN 128
#define BK 64
#define NCHUNK (KP4/BK)         // 64

// smem layout (bytes): A ring 2 x 16K (computed in-kernel),
// B ring 3 x 16K (cp.async), X ring 3 x 8K (cp.async raw x slices)
#define A_OFF 0
#define A_STG 16384
#define B_OFF 32768
#define B_STG 16384
#define X_OFF 81920
#define X_STG 8192
#define SMEM_DYN 106496          // 104 KB -> 2 CTAs/SM

// ============================================================
// Device scratch (allocation-free rule: __device__ globals)
// ============================================================
__device__ __align__(16) __half g_B[(size_t)NO * KP4];   // [o][i*4+t] imp*coeffs(j=t+1)

// ============================================================
// PTX helpers
// ============================================================
__device__ __forceinline__ uint32_t smem_u32(const void* p) {
    uint32_t a;
    asm("{ .reg .u64 t; cvta.to.shared.u64 t, %1; cvt.u32.u64 %0, t; }" : "=r"(a) : "l"(p));
    return a;
}
__device__ __forceinline__ void cp16(uint32_t dst, const void* src) {
    asm volatile("cp.async.cg.shared.global [%0], [%1], 16;" :: "r"(dst), "l"(src));
}
__device__ __forceinline__ void cp_commit() { asm volatile("cp.async.commit_group;"); }
template <int N> __device__ __forceinline__ void cp_wait() {
    asm volatile("cp.async.wait_group %0;" :: "n"(N));
}
__device__ __forceinline__ void ldmx4(uint32_t& r0, uint32_t& r1, uint32_t& r2, uint32_t& r3,
                                      uint32_t addr) {
    asm volatile("ldmatrix.sync.aligned.m8n8.x4.shared.b16 {%0,%1,%2,%3}, [%4];"
                 : "=r"(r0), "=r"(r1), "=r"(r2), "=r"(r3) : "r"(addr));
}
__device__ __forceinline__ void lds128f(float& a, float& b, float& c, float& d, uint32_t addr) {
    asm volatile("ld.shared.v4.f32 {%0,%1,%2,%3}, [%4];"
                 : "=f"(a), "=f"(b), "=f"(c), "=f"(d) : "r"(addr));
}
__device__ __forceinline__ void sts128(uint32_t addr, uint32_t a, uint32_t b, uint32_t c, uint32_t d) {
    asm volatile("st.shared.v4.b32 [%0], {%1,%2,%3,%4};"
                 :: "r"(addr), "r"(a), "r"(b), "r"(c), "r"(d) : "memory");
}
__device__ __forceinline__ void mma16816(float* c,
                                         uint32_t a0, uint32_t a1, uint32_t a2, uint32_t a3,
                                         uint32_t b0, uint32_t b1) {
    asm volatile(
        "mma.sync.aligned.m16n8k16.row.col.f32.f16.f16.f32 "
        "{%0,%1,%2,%3}, {%4,%5,%6,%7}, {%8,%9}, {%0,%1,%2,%3};"
        : "+f"(c[0]), "+f"(c[1]), "+f"(c[2]), "+f"(c[3])
        : "r"(a0), "r"(a1), "r"(a2), "r"(a3), "r"(b0), "r"(b1));
}

// ============================================================
// Closed-form uniform cubic B-spline (knots linspace(-1,1,9), x in [0,1)):
// s4 = floor(4x), u = frac(4x); nonzero basis j = s4+1..min(s4+4,4);
// zeros form a PREFIX of the 4 stored slots (pure selects).
// Computes 8 consecutive i-values for one (row r, half h) and stores the
// 64B run into the swizzled A tile at sts row base.
// ============================================================
__device__ __forceinline__ void basis8_sts(const float xv[8], uint32_t a_rowbase,
                                           int r, int h) {
    uint32_t wpq[4][4];
#pragma unroll
    for (int e = 0; e < 8; e++) {
        float xx = 4.0f * xv[e];
        float s4f = floorf(xx);
        s4f = fminf(fmaxf(s4f, 0.0f), 3.0f);
        int s4 = (int)s4f;
        float u = xx - s4f;
        float u2 = u * u, u3 = u2 * u;
        float omu = 1.0f - u;
        const float c6 = 1.0f / 6.0f;
        float v0 = omu * omu * omu * c6;
        float v1 = (3.0f * u3 - 6.0f * u2 + 4.0f) * c6;
        float v2 = (-3.0f * u3 + 3.0f * u2 + 3.0f * u + 1.0f) * c6;
        float v3 = u3 * c6;
        float h0 = (s4 == 0) ? v0 : 0.0f;
        float h1 = (s4 == 0) ? v1 : (s4 == 1) ? v0 : 0.0f;
        float h2 = (s4 == 0) ? v2 : (s4 == 1) ? v1 : (s4 == 2) ? v0 : 0.0f;
        float h3 = (s4 == 0) ? v3 : (s4 == 1) ? v2 : (s4 == 2) ? v1 : v0;
        __half2 p0 = __floats2half2_rn(h0, h1);
        __half2 p1 = __floats2half2_rn(h2, h3);
        wpq[e >> 1][(e & 1) * 2 + 0] = *(uint32_t*)&p0;
        wpq[e >> 1][(e & 1) * 2 + 1] = *(uint32_t*)&p1;
    }
#pragma unroll
    for (int q = 0; q < 4; q++) {
        int cc = h * 4 + q;
        sts128(a_rowbase + (((cc ^ (r & 7)) << 4)),
               wpq[q][0], wpq[q][1], wpq[q][2], wpq[q][3]);
    }
}

// ============================================================
// Kernel: w = importance * coeffs (j=1..4), transposed to [o][i*4+t] fp16.
// ============================================================
__global__ void __launch_bounds__(256) prep_w(const float* __restrict__ coeffs,
                                              const float* __restrict__ imp) {
    __shared__ float sc[32 * 161];   // [il][ol*5+k], row stride 161 (conflict-free)
    __shared__ float si[32 * 33];    // [il][ol],     row stride 33
    int bid = blockIdx.x;
    int tid = threadIdx.x;
    int i0 = (bid & 31) * 32;
    int o0 = (bid >> 5) * 32;

    for (int e = tid; e < 32 * 160; e += 256) {
        int il = e / 160, r = e - il * 160;
        sc[il * 161 + r] = coeffs[((size_t)(i0 + il) * NO + o0) * K5 + r];
    }
    for (int e = tid; e < 1024; e += 256) {
        int il = e >> 5, ol = e & 31;
        si[il * 33 + ol] = imp[(size_t)(i0 + il) * NO + o0 + ol];
    }
    __syncthreads();

    for (int f = tid; f < 1024; f += 256) {
        int ol = f >> 5, il = f & 31;
        float s = si[il * 33 + ol];
        const float* cp = &sc[il * 161 + ol * 5 + 1];  // skip j=0 (always 0)
        __half2 lo = __floats2half2_rn(cp[0] * s, cp[1] * s);
        __half2 hi = __floats2half2_rn(cp[2] * s, cp[3] * s);
        uint2 v;
        v.x = *(uint32_t*)&lo;
        v.y = *(uint32_t*)&hi;
        *(uint2*)(g_B + (size_t)(o0 + ol) * KP4 + (size_t)(i0 + il) * 4) = v;
    }
}

// ============================================================
// Fused GEMM: out = basis(x) @ B^T, basis computed in-kernel.
// Pipeline: cp.async group g carries B[g] tile + raw x slice for chunk g+1.
// At iter kt: build A[kt+1] from x-smem (ALU work hidden under tensor pipe),
// run MMAs on A[kt] (2-stage A ring) and B[kt] (3-stage B ring).
// ============================================================
__global__ void __launch_bounds__(256, 2) kan_gemm(const float* __restrict__ x,
                                                   float* __restrict__ out) {
    extern __shared__ char smem[];
    const int tid = threadIdx.x;
    const int wid = tid >> 5, lane = tid & 31;
    const int wr = wid >> 1, wc = wid & 1;   // warp grid 4 (M) x 2 (N)
    const int m0 = blockIdx.x * BM, n0 = blockIdx.y * BN;

    float acc[2][8][4];
#pragma unroll
    for (int i = 0; i < 2; i++)
#pragma unroll
        for (int j = 0; j < 8; j++)
#pragma unroll
            for (int q = 0; q < 4; q++) acc[i][j][q] = 0.f;

    const uint32_t sbase = smem_u32(smem);
    const int xr = tid >> 1;          // basis row 0..127
    const int xh = tid & 1;           // 8-i half

    // group kt: B tile for chunk kt + x slice for chunk kt+1
    auto issue = [&](int kt) {
#pragma unroll
        for (int i = 0; i < 4; i++) {           // B: 1024 16B chunks
            int cb = tid + i * 256;
            int r = cb >> 3, cc = cb & 7;
            cp16(sbase + B_OFF + (kt % 3) * B_STG + r * 128 + (((cc ^ (r & 7)) << 4)),
                 g_B + (size_t)(n0 + r) * KP4 + kt * BK + cc * 8);
        }
        if (kt + 1 < NCHUNK) {                  // x: 512 16B chunks
#pragma unroll
            for (int i = 0; i < 2; i++) {
                int c = tid + i * 256;
                int r = c >> 2, q = c & 3;
                cp16(sbase + X_OFF + ((kt + 1) % 3) * X_STG + r * 64 + q * 16,
                     x + (size_t)(m0 + r) * NI + (kt + 1) * 16 + q * 4);
            }
        }
        cp_commit();
    };

    // Prologue: A[0] computed directly from gmem x
    {
        float xv[8];
        const float* xp = x + (size_t)(m0 + xr) * NI + xh * 8;
        float4 va = *(const float4*)xp;
        float4 vb = *(const float4*)(xp + 4);
        xv[0] = va.x; xv[1] = va.y; xv[2] = va.z; xv[3] = va.w;
        xv[4] = vb.x; xv[5] = vb.y; xv[6] = vb.z; xv[7] = vb.w;
        basis8_sts(xv, sbase + A_OFF + 0 * A_STG + xr * 128, xr, xh);
    }
    issue(0);
    issue(1);

    const int lrow = lane & 15;
    const int lhalf = lane >> 4;
    const int lxor = lrow & 7;

    uint32_t af[2][2][4];   // [buf][mi][reg]
    uint32_t bf[2][4][4];   // [buf][g][reg]

    for (int kt = 0; kt < NCHUNK; kt++) {
        if (kt < NCHUNK - 1) cp_wait<1>(); else cp_wait<0>();
        __syncthreads();
        if (kt + 2 < NCHUNK) issue(kt + 2);

        // Build A[kt+1] from the x slice that landed with group kt
        if (kt + 1 < NCHUNK) {
            float xv[8];
            uint32_t xsrc = sbase + X_OFF + ((kt + 1) % 3) * X_STG + xr * 64 + xh * 32;
            lds128f(xv[0], xv[1], xv[2], xv[3], xsrc);
            lds128f(xv[4], xv[5], xv[6], xv[7], xsrc + 16);
            basis8_sts(xv, sbase + A_OFF + ((kt + 1) & 1) * A_STG + xr * 128, xr, xh);
        }

        uint32_t as = sbase + A_OFF + (kt & 1) * A_STG;
        uint32_t bs = sbase + B_OFF + (kt % 3) * B_STG;

        // frag prologue: ks=0 into buf 0
        {
            int cc = (0 * 2 + lhalf) ^ lxor;
#pragma unroll
            for (int mi = 0; mi < 2; mi++) {
                int r = wr * 32 + mi * 16 + lrow;
                ldmx4(af[0][mi][0], af[0][mi][1], af[0][mi][2], af[0][mi][3],
                      as + r * 128 + cc * 16);
            }
#pragma unroll
            for (int g = 0; g < 4; g++) {
                int r = wc * 64 + g * 16 + lrow;
                ldmx4(bf[0][g][0], bf[0][g][1], bf[0][g][2], bf[0][g][3],
                      bs + r * 128 + cc * 16);
            }
        }

#pragma unroll
        for (int ks = 0; ks < 4; ks++) {
            int buf = ks & 1;
            if (ks < 3) {                     // prefetch next ks into other buf
                int nb = buf ^ 1;
                int cc = ((ks + 1) * 2 + lhalf) ^ lxor;
#pragma unroll
                for (int mi = 0; mi < 2; mi++) {
                    int r = wr * 32 + mi * 16 + lrow;
                    ldmx4(af[nb][mi][0], af[nb][mi][1], af[nb][mi][2], af[nb][mi][3],
                          as + r * 128 + cc * 16);
                }
#pragma unroll
                for (int g = 0; g < 4; g++) {
                    int r = wc * 64 + g * 16 + lrow;
                    ldmx4(bf[nb][g][0], bf[nb][g][1], bf[nb][g][2], bf[nb][g][3],
                          bs + r * 128 + cc * 16);
                }
            }
#pragma unroll
            for (int g = 0; g < 4; g++) {
#pragma unroll
                for (int mi = 0; mi < 2; mi++) {
                    mma16816(acc[mi][g * 2 + 0],
                             af[buf][mi][0], af[buf][mi][1], af[buf][mi][2], af[buf][mi][3],
                             bf[buf][g][0], bf[buf][g][2]);
                    mma16816(acc[mi][g * 2 + 1],
                             af[buf][mi][0], af[buf][mi][1], af[buf][mi][2], af[buf][mi][3],
                             bf[buf][g][1], bf[buf][g][3]);
                }
            }
        }
    }

    // Epilogue: frag rows lane/4 (+8), cols 2*(lane%4)+{0,1}
    const int lr = lane >> 2;
    const int lc = (lane & 3) * 2;
#pragma unroll
    for (int mi = 0; mi < 2; mi++) {
#pragma unroll
        for (int nf = 0; nf < 8; nf++) {
            int row = m0 + wr * 32 + mi * 16 + lr;
            int col = n0 + wc * 64 + nf * 8 + lc;
            float* p = out + (size_t)row * NO + col;
            *(float2*)p = make_float2(acc[mi][nf][0], acc[mi][nf][1]);
            *(float2*)(p + 8 * NO) = make_float2(acc[mi][nf][2], acc[mi][nf][3]);
        }
    }
}

// ============================================================
// Launch
// ============================================================
extern "C" void kernel_launch(void* const* d_in, const int* in_sizes, int n_in,
                              void* d_out, int out_size) {
    const float* x = nullptr;
    const float* coeffs = nullptr;
    const float* imp = nullptr;
    for (int i = 0; i < n_in; i++) {
        if (in_sizes[i] == NB * NI) x = (const float*)d_in[i];
        else if (in_sizes[i] == NI * NO * K5) coeffs = (const float*)d_in[i];
        else if (in_sizes[i] == NI * NO) imp = (const float*)d_in[i];
    }

    prep_w<<<(NI / 32) * (NO / 32), 256>>>(coeffs, imp);

    static int smem_set = 0;
    if (!smem_set) {
        cudaFuncSetAttribute(kan_gemm, cudaFuncAttributeMaxDynamicSharedMemorySize, SMEM_DYN);
        smem_set = 1;
    }
    kan_gemm<<<dim3(NB / BM, NO / BN), 256, SMEM_DYN>>>(x, (float*)d_out);
}

// round 9
// speedup vs baseline: 1.4260x; 1.4260x over previous
#include <cuda_runtime.h>
#include <cuda_fp16.h>
#include <cstdint>

// ============================================================
// Problem constants
// ============================================================
#define NB 4096   // batch
#define NI 1024   // input dim
#define NO 1024   // output dim
#define K5 5      // control points per edge (j=0 basis column identically 0)
#define K4 4      // effective nonzero control points
#define KP4 (NI*K4)  // 4096 = effective GEMM reduction dim

// GEMM tiling: BM=BN=128, BK=64, 256 threads, 2 CTAs/SM, 3-stage cp.async
#define BM 128
#define BN 128
#define BK 64
#define NSTAGE 3
#define CHUNKS_PER_TILE (KP4/BK)     // 64
#define NTILE ((NB/BM)*(NO/BN))      // 256
#define GU (NTILE*CHUNKS_PER_TILE)   // 16384 flat chunk-units
#define NCTA 296                     // = 148 SMs x 2 CTAs -> perfectly balanced

#define AS_BYTES (BM*BK*2)      // 16384
#define BS_BYTES (BN*BK*2)      // 16384
#define STAGE_BYTES (AS_BYTES + BS_BYTES)   // 32768
#define SMEM_DYN (NSTAGE*STAGE_BYTES)       // 98304 -> 2 CTAs/SM

// ============================================================
// Device scratch (allocation-free rule: __device__ globals)
// ============================================================
__device__ __align__(16) __half g_A[(size_t)NB * KP4];   // [b][i*4+t] basis(j=t+1)
__device__ __align__(16) __half g_B[(size_t)NO * KP4];   // [o][i*4+t] imp*coeffs(j=t+1)

// ============================================================
// PTX helpers
// ============================================================
__device__ __forceinline__ uint32_t smem_u32(const void* p) {
    uint32_t a;
    asm("{ .reg .u64 t; cvta.to.shared.u64 t, %1; cvt.u32.u64 %0, t; }" : "=r"(a) : "l"(p));
    return a;
}
__device__ __forceinline__ void cp16(uint32_t dst, const void* src) {
    asm volatile("cp.async.cg.shared.global [%0], [%1], 16;" :: "r"(dst), "l"(src));
}
__device__ __forceinline__ void cp_commit() { asm volatile("cp.async.commit_group;"); }
template <int N> __device__ __forceinline__ void cp_wait() {
    asm volatile("cp.async.wait_group %0;" :: "n"(N));
}
__device__ __forceinline__ void ldmx4(uint32_t& r0, uint32_t& r1, uint32_t& r2, uint32_t& r3,
                                      uint32_t addr) {
    asm volatile("ldmatrix.sync.aligned.m8n8.x4.shared.b16 {%0,%1,%2,%3}, [%4];"
                 : "=r"(r0), "=r"(r1), "=r"(r2), "=r"(r3) : "r"(addr));
}
__device__ __forceinline__ void mma16816(float* c,
                                         uint32_t a0, uint32_t a1, uint32_t a2, uint32_t a3,
                                         uint32_t b0, uint32_t b1) {
    asm volatile(
        "mma.sync.aligned.m16n8k16.row.col.f32.f16.f16.f32 "
        "{%0,%1,%2,%3}, {%4,%5,%6,%7}, {%8,%9}, {%0,%1,%2,%3};"
        : "+f"(c[0]), "+f"(c[1]), "+f"(c[2]), "+f"(c[3])
        : "r"(a0), "r"(a1), "r"(a2), "r"(a3), "r"(b0), "r"(b1));
}

// ============================================================
// Kernel 1: closed-form uniform cubic B-spline basis -> g_A fp16,
// plus zero-init of out (needed by the atomic stream-K epilogue).
// x in [0,1): s4 = floor(4x), u = frac(4x); zeros form a PREFIX of the
// 4 stored slots: h[t] = v[t-s4] for t>=s4 else 0 (pure selects).
// 4 elems/thread: float4 in, 2x uint4 out.
// ============================================================
__global__ void __launch_bounds__(256) prep_basis(const float* __restrict__ x,
                                                  float* __restrict__ out) {
    int t = blockIdx.x * 256 + threadIdx.x;
    // zero out: 4096 blocks x 256 thr x 1 float4 = 4M floats
    ((float4*)out)[t] = make_float4(0.f, 0.f, 0.f, 0.f);

    int e0 = t * 4;
    float4 xv = *(const float4*)(x + e0);
    float xs[4] = {xv.x, xv.y, xv.z, xv.w};
    uint4 outv[2];
    uint32_t* wp = (uint32_t*)outv;   // 8 half2 words
#pragma unroll
    for (int e = 0; e < 4; e++) {
        float xx = 4.0f * xs[e];
        float s4f = floorf(xx);
        s4f = fminf(fmaxf(s4f, 0.0f), 3.0f);
        int s4 = (int)s4f;
        float u = xx - s4f;
        float u2 = u * u, u3 = u2 * u;
        float omu = 1.0f - u;
        const float c6 = 1.0f / 6.0f;
        float v0 = omu * omu * omu * c6;
        float v1 = (3.0f * u3 - 6.0f * u2 + 4.0f) * c6;
        float v2 = (-3.0f * u3 + 3.0f * u2 + 3.0f * u + 1.0f) * c6;
        float v3 = u3 * c6;
        float h0 = (s4 == 0) ? v0 : 0.0f;
        float h1 = (s4 == 0) ? v1 : (s4 == 1) ? v0 : 0.0f;
        float h2 = (s4 == 0) ? v2 : (s4 == 1) ? v1 : (s4 == 2) ? v0 : 0.0f;
        float h3 = (s4 == 0) ? v3 : (s4 == 1) ? v2 : (s4 == 2) ? v1 : v0;
        __half2 p0 = __floats2half2_rn(h0, h1);
        __half2 p1 = __floats2half2_rn(h2, h3);
        wp[e * 2 + 0] = *(uint32_t*)&p0;
        wp[e * 2 + 1] = *(uint32_t*)&p1;
    }
    uint4* dst = (uint4*)(g_A + (size_t)e0 * K4);
    dst[0] = outv[0];
    dst[1] = outv[1];
}

// ============================================================
// Kernel 2: w = importance * coeffs (j=1..4), transposed to [o][i*4+t] fp16.
// 32x32 (i,o) tile; padded smem rows (161/33 floats) => conflict-free.
// ============================================================
__global__ void __launch_bounds__(256) prep_w(const float* __restrict__ coeffs,
                                              const float* __restrict__ imp) {
    __shared__ float sc[32 * 161];   // [il][ol*5+k], row stride 161
    __shared__ float si[32 * 33];    // [il][ol],     row stride 33
    int bid = blockIdx.x;
    int tid = threadIdx.x;
    int i0 = (bid & 31) * 32;
    int o0 = (bid >> 5) * 32;

    for (int e = tid; e < 32 * 160; e += 256) {
        int il = e / 160, r = e - il * 160;
        sc[il * 161 + r] = coeffs[((size_t)(i0 + il) * NO + o0) * K5 + r];
    }
    for (int e = tid; e < 1024; e += 256) {
        int il = e >> 5, ol = e & 31;
        si[il * 33 + ol] = imp[(size_t)(i0 + il) * NO + o0 + ol];
    }
    __syncthreads();

    for (int f = tid; f < 1024; f += 256) {
        int ol = f >> 5, il = f & 31;
        float s = si[il * 33 + ol];
        const float* cp = &sc[il * 161 + ol * 5 + 1];  // skip j=0 (always 0)
        __half2 lo = __floats2half2_rn(cp[0] * s, cp[1] * s);
        __half2 hi = __floats2half2_rn(cp[2] * s, cp[3] * s);
        uint2 v;
        v.x = *(uint32_t*)&lo;
        v.y = *(uint32_t*)&hi;
        *(uint2*)(g_B + (size_t)(o0 + ol) * KP4 + (size_t)(i0 + il) * 4) = v;
    }
}

// ============================================================
// Stream-K GEMM: 16384 flat chunk-units over exactly 296 CTAs (2/SM,
// perfectly balanced). Each CTA's contiguous span crosses <= 2 tiles;
// per tile-segment: 3-stage cp.async pipeline + register-double-buffered
// ldmatrix/mma inner loop (proven round-5/7 core), epilogue atomicAdd
// into zero-initialized out.
// ============================================================
__global__ void __launch_bounds__(256, 2) kan_gemm(float* __restrict__ out) {
    extern __shared__ char smem[];
    const int tid = threadIdx.x;
    const int wid = tid >> 5, lane = tid & 31;
    const int wr = wid >> 1, wc = wid & 1;   // warp grid 4 (M) x 2 (N)
    const uint32_t sbase = smem_u32(smem);

    const int lrow = lane & 15;
    const int lhalf = lane >> 4;
    const int lxor = lrow & 7;
    const int lr = lane >> 2;
    const int lc = (lane & 3) * 2;

    const int c = blockIdx.x;
    int g  = (int)(((long long)c * GU) / NCTA);
    int ge = (int)(((long long)(c + 1) * GU) / NCTA);

    while (g < ge) {
        const int tile = g >> 6;                       // /CHUNKS_PER_TILE
        const int k0 = g & 63;
        const int nk = min(ge, (tile + 1) * CHUNKS_PER_TILE) - g;
        const int m0 = (tile >> 3) * BM;               // tm = tile/8
        const int n0 = (tile & 7) * BN;

        float acc[2][8][4];
#pragma unroll
        for (int i = 0; i < 2; i++)
#pragma unroll
            for (int j = 0; j < 8; j++)
#pragma unroll
                for (int q = 0; q < 4; q++) acc[i][j][q] = 0.f;

        auto issue = [&](int j) {                      // chunk k0+j -> stage j%3
            uint32_t as = sbase + (j % NSTAGE) * STAGE_BYTES;
            uint32_t bs = as + AS_BYTES;
            int koff = (k0 + j) * BK;
#pragma unroll
            for (int i = 0; i < 4; i++) {              // A: 1024 16B chunks
                int ca = tid + i * 256;
                int r = ca >> 3, cc = ca & 7;
                cp16(as + r * 128 + (((cc ^ (r & 7)) << 4)),
                     g_A + (size_t)(m0 + r) * KP4 + koff + cc * 8);
            }
#pragma unroll
            for (int i = 0; i < 4; i++) {              // B: 1024 16B chunks
                int cb = tid + i * 256;
                int r = cb >> 3, cc = cb & 7;
                cp16(bs + r * 128 + (((cc ^ (r & 7)) << 4)),
                     g_B + (size_t)(n0 + r) * KP4 + koff + cc * 8);
            }
            cp_commit();
        };

        __syncthreads();          // protect smem from previous segment's readers
        issue(0);
        if (nk > 1) issue(1);

        uint32_t af[2][2][4];     // [buf][mi][reg]
        uint32_t bf[2][4][4];     // [buf][g][reg]

        for (int kt = 0; kt < nk; kt++) {
            if (kt < nk - 1) cp_wait<1>(); else cp_wait<0>();
            __syncthreads();
            if (kt + 2 < nk) issue(kt + 2);

            uint32_t as = sbase + (kt % NSTAGE) * STAGE_BYTES;
            uint32_t bs = as + AS_BYTES;

            // frag prologue: ks=0 into buf 0
            {
                int cc = (0 * 2 + lhalf) ^ lxor;
#pragma unroll
                for (int mi = 0; mi < 2; mi++) {
                    int r = wr * 32 + mi * 16 + lrow;
                    ldmx4(af[0][mi][0], af[0][mi][1], af[0][mi][2], af[0][mi][3],
                          as + r * 128 + cc * 16);
                }
#pragma unroll
                for (int gg = 0; gg < 4; gg++) {
                    int r = wc * 64 + gg * 16 + lrow;
                    ldmx4(bf[0][gg][0], bf[0][gg][1], bf[0][gg][2], bf[0][gg][3],
                          bs + r * 128 + cc * 16);
                }
            }

#pragma unroll
            for (int ks = 0; ks < 4; ks++) {
                int buf = ks & 1;
                if (ks < 3) {                 // prefetch next ks into other buf
                    int nb = buf ^ 1;
                    int cc = ((ks + 1) * 2 + lhalf) ^ lxor;
#pragma unroll
                    for (int mi = 0; mi < 2; mi++) {
                        int r = wr * 32 + mi * 16 + lrow;
                        ldmx4(af[nb][mi][0], af[nb][mi][1], af[nb][mi][2], af[nb][mi][3],
                              as + r * 128 + cc * 16);
                    }
#pragma unroll
                    for (int gg = 0; gg < 4; gg++) {
                        int r = wc * 64 + gg * 16 + lrow;
                        ldmx4(bf[nb][gg][0], bf[nb][gg][1], bf[nb][gg][2], bf[nb][gg][3],
                              bs + r * 128 + cc * 16);
                    }
                }
#pragma unroll
                for (int gg = 0; gg < 4; gg++) {
#pragma unroll
                    for (int mi = 0; mi < 2; mi++) {
                        mma16816(acc[mi][gg * 2 + 0],
                                 af[buf][mi][0], af[buf][mi][1], af[buf][mi][2], af[buf][mi][3],
                                 bf[buf][gg][0], bf[buf][gg][2]);
                        mma16816(acc[mi][gg * 2 + 1],
                                 af[buf][mi][0], af[buf][mi][1], af[buf][mi][2], af[buf][mi][3],
                                 bf[buf][gg][1], bf[buf][gg][3]);
                    }
                }
            }
        }

        // segment epilogue: accumulate partial tile into out
#pragma unroll
        for (int mi = 0; mi < 2; mi++) {
#pragma unroll
            for (int nf = 0; nf < 8; nf++) {
                int row = m0 + wr * 32 + mi * 16 + lr;
                int col = n0 + wc * 64 + nf * 8 + lc;
                float* p = out + (size_t)row * NO + col;
                atomicAdd(p + 0, acc[mi][nf][0]);
                atomicAdd(p + 1, acc[mi][nf][1]);
                atomicAdd(p + 8 * NO + 0, acc[mi][nf][2]);
                atomicAdd(p + 8 * NO + 1, acc[mi][nf][3]);
            }
        }

        g += nk;
    }
}

// ============================================================
// Launch
// ============================================================
extern "C" void kernel_launch(void* const* d_in, const int* in_sizes, int n_in,
                              void* d_out, int out_size) {
    const float* x = nullptr;
    const float* coeffs = nullptr;
    const float* imp = nullptr;
    for (int i = 0; i < n_in; i++) {
        if (in_sizes[i] == NB * NI) x = (const float*)d_in[i];
        else if (in_sizes[i] == NI * NO * K5) coeffs = (const float*)d_in[i];
        else if (in_sizes[i] == NI * NO) imp = (const float*)d_in[i];
    }

    prep_basis<<<(NB * NI) / 1024, 256>>>(x, (float*)d_out);
    prep_w<<<(NI / 32) * (NO / 32), 256>>>(coeffs, imp);

    static int smem_set = 0;
    if (!smem_set) {
        cudaFuncSetAttribute(kan_gemm, cudaFuncAttributeMaxDynamicSharedMemorySize, SMEM_DYN);
        smem_set = 1;
    }
    kan_gemm<<<NCTA, 256, SMEM_DYN>>>((float*)d_out);
}